// round 13
// baseline (speedup 1.0000x reference)
#include <cuda_runtime.h>
#include <cstdint>

// ============================================================================
// TernaryLinear: out[8192,4096] = x[8192,4096] @ W^T[4096,4096] + bias
//
// sm_103 plain PTX target -> legacy IMMA path (tcgen05 rejected by ptxas).
// Two exact int8 GEMMs (x = s1*a1 + (s1/254)*a2), int32 accumulation.
// Floor: 67M m16n8k32 IMMA @ ~13.6 cyc/SM ~= 3.47 ms.
// R8: 2 CTAs/SM -> 92.5% tensor busy.  R9 change: persistent CTAs
// (grid=296, 2/SM) with a FLAT chunk index so the 3-stage cp.async pipeline
// runs continuously across tile boundaries: no per-tile prologue stall, and
// epilogues overlap with next-tile prefetch.
// ============================================================================

static constexpr int M = 8192, N = 4096, K = 4096;

static constexpr int BM = 128, BN = 128, BK = 128;
static constexpr int KCH = K / BK;            // 32 k-chunks per tile
static constexpr int NSTG = 3;
static constexpr int APITCH = BK + 16;        // 144: bank = lane (conflict-free)
static constexpr int BPITCH = BK + 16;
static constexpr int STG_A = BM * APITCH;     // 18432
static constexpr int STG_B = BN * BPITCH;     // 18432
static constexpr int STG = STG_A + STG_B;     // 36864
static constexpr int SMEM_BYTES = STG * NSTG; // 110592 (x2 CTA = 221184 <= 228K)

static constexpr int NTILES = (M / BM) * (N / BN);  // 2048
static constexpr int GRID = 296;                    // 2 CTAs x 148 SMs

// ---------------------------------------------------------------------------
// Static device scratch (allocation is forbidden)
// ---------------------------------------------------------------------------
__device__ __align__(16) int8_t g_a1[(size_t)M * K];   // 32 MB
__device__ __align__(16) int8_t g_a2[(size_t)M * K];   // 32 MB
__device__ __align__(16) int8_t g_wq[(size_t)N * K];   // 16 MB
__device__ __align__(16) int    g_o1[(size_t)M * N];   // 128 MB
__device__ float g_s1[M];

// ---------------------------------------------------------------------------
// Quantization kernels
// ---------------------------------------------------------------------------
__global__ __launch_bounds__(256) void quant_x(const float* __restrict__ x) {
    const int row = blockIdx.x;
    const int t = threadIdx.x;
    const float* xr = x + (size_t)row * K;

    float v[16];
#pragma unroll
    for (int i = 0; i < 4; i++) {
        float4 f = *reinterpret_cast<const float4*>(xr + t * 16 + i * 4);
        v[i * 4 + 0] = f.x; v[i * 4 + 1] = f.y;
        v[i * 4 + 2] = f.z; v[i * 4 + 3] = f.w;
    }
    float mx = 0.f;
#pragma unroll
    for (int i = 0; i < 16; i++) mx = fmaxf(mx, fabsf(v[i]));

    __shared__ float red[256];
    red[t] = mx;
    __syncthreads();
#pragma unroll
    for (int s = 128; s > 0; s >>= 1) {
        if (t < s) red[t] = fmaxf(red[t], red[t + s]);
        __syncthreads();
    }
    const float rmax = red[0];
    const float s1 = rmax * (1.f / 127.f);
    const float inv1 = (rmax > 0.f) ? (127.f / rmax) : 0.f;
    const float inv2 = inv1 * 254.f;
    if (t == 0) g_s1[row] = s1;

    uint32_t p1[4] = {0, 0, 0, 0}, p2[4] = {0, 0, 0, 0};
#pragma unroll
    for (int i = 0; i < 16; i++) {
        int a = __float2int_rn(v[i] * inv1);
        a = max(-127, min(127, a));
        float r = v[i] - (float)a * s1;
        int b = __float2int_rn(r * inv2);
        b = max(-127, min(127, b));
        p1[i >> 2] |= ((uint32_t)a & 0xffu) << (8 * (i & 3));
        p2[i >> 2] |= ((uint32_t)b & 0xffu) << (8 * (i & 3));
    }
    const size_t off = (size_t)row * K + t * 16;
    *reinterpret_cast<uint4*>(g_a1 + off) = *reinterpret_cast<uint4*>(p1);
    *reinterpret_cast<uint4*>(g_a2 + off) = *reinterpret_cast<uint4*>(p2);
}

__global__ __launch_bounds__(256) void quant_w(const float* __restrict__ w) {
    const size_t base = ((size_t)blockIdx.x * 256 + threadIdx.x) * 16;
    uint32_t p[4];
#pragma unroll
    for (int i = 0; i < 4; i++) {
        float4 f = *reinterpret_cast<const float4*>(w + base + i * 4);
        int a = __float2int_rn(f.x), b = __float2int_rn(f.y);
        int c = __float2int_rn(f.z), d = __float2int_rn(f.w);
        p[i] = ((uint32_t)a & 0xffu) | (((uint32_t)b & 0xffu) << 8) |
               (((uint32_t)c & 0xffu) << 16) | (((uint32_t)d & 0xffu) << 24);
    }
    *reinterpret_cast<uint4*>(g_wq + base) = *reinterpret_cast<uint4*>(p);
}

// ---------------------------------------------------------------------------
// IMMA helpers
// ---------------------------------------------------------------------------
__device__ __forceinline__ void imma16832(int* c, const uint32_t* a, const uint32_t* b) {
    asm volatile(
        "mma.sync.aligned.m16n8k32.row.col.s32.s8.s8.s32 "
        "{%0,%1,%2,%3}, {%4,%5,%6,%7}, {%8,%9}, {%0,%1,%2,%3};"
        : "+r"(c[0]), "+r"(c[1]), "+r"(c[2]), "+r"(c[3])
        : "r"(a[0]), "r"(a[1]), "r"(a[2]), "r"(a[3]), "r"(b[0]), "r"(b[1]));
}

__device__ __forceinline__ void cp16(void* s, const void* g) {
    uint32_t sa = (uint32_t)__cvta_generic_to_shared(s);
    asm volatile("cp.async.cg.shared.global [%0], [%1], 16;" :: "r"(sa), "l"(g));
}

__device__ __forceinline__ uint32_t lds32(const void* p) {
    return *reinterpret_cast<const uint32_t*>(p);
}

// ---------------------------------------------------------------------------
// Persistent GEMM: grid=296, 2 CTAs/SM; each CTA walks tiles bid, bid+296, ...
// over a flat chunk index so the pipeline never drains between tiles.
// pass=0: o1 = a1.W (int32). pass=1: out = s1*o1 + s2*(a2.W) + bias.
// ---------------------------------------------------------------------------
__global__ __launch_bounds__(256, 2)
void gemm_s8(int pass, float* __restrict__ out, const float* __restrict__ bias) {
    extern __shared__ char smem[];
    const int tid = threadIdx.x;
    const int warp = tid >> 5, lane = tid & 31;
    const int g = lane >> 2, tig = lane & 3;     // mma group / thread-in-group
    const int bid = blockIdx.x;

    const int wm = (warp & 1) * 64;              // warp tile origin 64x32
    const int wn = (warp >> 1) * 32;

    const int8_t* Abase = pass ? g_a2 : g_a1;

    const int ntile_loc = (NTILES - bid + GRID - 1) / GRID;
    const int total = ntile_loc * KCH;           // flat chunk count

    // ---- flat-index stage loader -----------------------------------------
    auto load_flat = [&](int fi) {
        int s = fi;
        while (s >= NSTG) s -= NSTG;             // stage = fi mod 3
        const int j = fi >> 5;                   // local tile ordinal
        const int ch = fi & (KCH - 1);
        const int t = bid + j * GRID;
        const int bn = t & 31, bm = t >> 5;      // n-fast tile order
        const int8_t* Ap = Abase + (size_t)(bm * BM) * K;
        const int8_t* Wp = g_wq + (size_t)(bn * BN) * K;
        char* st = smem + s * STG;
        const int k0 = ch * BK;
#pragma unroll
        for (int it = 0; it < 8; it++) {
            const int item = tid + it * 256;     // 0..2047
            if (item < 1024) {                   // A: 128 rows x 8 segs
                const int row = item >> 3, seg = item & 7;
                cp16(st + row * APITCH + seg * 16,
                     Ap + (size_t)row * K + k0 + seg * 16);
            } else {                             // B: 128 rows x 8 segs
                const int bi = item - 1024;
                const int row = bi >> 3, seg = bi & 7;
                cp16(st + STG_A + row * BPITCH + seg * 16,
                     Wp + (size_t)row * K + k0 + seg * 16);
            }
        }
        asm volatile("cp.async.commit_group;" ::: "memory");
    };

    // ---- accumulators: 4 mfrag x 4 nfrag x 4 = 64 regs --------------------
    int acc[4][4][4];
#pragma unroll
    for (int i = 0; i < 4; i++)
#pragma unroll
        for (int j = 0; j < 4; j++)
#pragma unroll
            for (int q = 0; q < 4; q++) acc[i][j][q] = 0;

    // ---- prologue: 2 chunks in flight ------------------------------------
    load_flat(0);
    load_flat(1);

    // ---- persistent mainloop ---------------------------------------------
    for (int i = 0; i < total; i++) {
        asm volatile("cp.async.wait_group 1;" ::: "memory");
        __syncthreads();
        if (i + 2 < total) load_flat(i + 2);
        else asm volatile("cp.async.commit_group;" ::: "memory");

        int cs = i;
        while (cs >= NSTG) cs -= NSTG;
        const char* As = smem + cs * STG;
        const char* Bs = As + STG_A;

#pragma unroll
        for (int ks = 0; ks < 4; ks++) {
            const int kb = ks * 32;
            uint32_t af[4][4];
#pragma unroll
            for (int mf = 0; mf < 4; mf++) {
                const char* ar = As + (wm + mf * 16 + g) * APITCH + kb + tig * 4;
                af[mf][0] = lds32(ar);
                af[mf][1] = lds32(ar + 8 * APITCH);
                af[mf][2] = lds32(ar + 16);
                af[mf][3] = lds32(ar + 8 * APITCH + 16);
            }
            uint32_t bf[4][2];
#pragma unroll
            for (int nf = 0; nf < 4; nf++) {
                const char* br = Bs + (wn + nf * 8 + g) * BPITCH + kb + tig * 4;
                bf[nf][0] = lds32(br);
                bf[nf][1] = lds32(br + 16);
            }
#pragma unroll
            for (int mf = 0; mf < 4; mf++)
#pragma unroll
                for (int nf = 0; nf < 4; nf++)
                    imma16832(acc[mf][nf], af[mf], bf[nf]);
        }

        // ---- tile finished? epilogue overlaps with in-flight prefetch -----
        if ((i & (KCH - 1)) == (KCH - 1)) {
            const int t = bid + (i >> 5) * GRID;
            const int m0 = (t >> 5) * BM, n0 = (t & 31) * BN;

            if (pass == 0) {
#pragma unroll
                for (int mf = 0; mf < 4; mf++) {
                    const int r0 = m0 + wm + mf * 16 + g;
#pragma unroll
                    for (int nf = 0; nf < 4; nf++) {
                        const int col = n0 + wn + nf * 8 + tig * 2;
                        *reinterpret_cast<int2*>(g_o1 + (size_t)r0 * N + col) =
                            make_int2(acc[mf][nf][0], acc[mf][nf][1]);
                        *reinterpret_cast<int2*>(g_o1 + (size_t)(r0 + 8) * N + col) =
                            make_int2(acc[mf][nf][2], acc[mf][nf][3]);
                        acc[mf][nf][0] = 0; acc[mf][nf][1] = 0;
                        acc[mf][nf][2] = 0; acc[mf][nf][3] = 0;
                    }
                }
            } else {
#pragma unroll
                for (int mf = 0; mf < 4; mf++) {
                    const int r0 = m0 + wm + mf * 16 + g;
                    const float s1a = g_s1[r0];
                    const float s1b = g_s1[r0 + 8];
                    const float s2a = s1a * (1.f / 254.f);
                    const float s2b = s1b * (1.f / 254.f);
#pragma unroll
                    for (int nf = 0; nf < 4; nf++) {
                        const int col = n0 + wn + nf * 8 + tig * 2;
                        const float2 bv = *reinterpret_cast<const float2*>(bias + col);
                        int2 oa = *reinterpret_cast<const int2*>(g_o1 + (size_t)r0 * N + col);
                        int2 ob = *reinterpret_cast<const int2*>(g_o1 + (size_t)(r0 + 8) * N + col);
                        float2 fa, fb;
                        fa.x = fmaf(s1a, (float)oa.x, fmaf(s2a, (float)acc[mf][nf][0], bv.x));
                        fa.y = fmaf(s1a, (float)oa.y, fmaf(s2a, (float)acc[mf][nf][1], bv.y));
                        fb.x = fmaf(s1b, (float)ob.x, fmaf(s2b, (float)acc[mf][nf][2], bv.x));
                        fb.y = fmaf(s1b, (float)ob.y, fmaf(s2b, (float)acc[mf][nf][3], bv.y));
                        *reinterpret_cast<float2*>(out + (size_t)r0 * N + col) = fa;
                        *reinterpret_cast<float2*>(out + (size_t)(r0 + 8) * N + col) = fb;
                        acc[mf][nf][0] = 0; acc[mf][nf][1] = 0;
                        acc[mf][nf][2] = 0; acc[mf][nf][3] = 0;
                    }
                }
            }
        }
    }
}

// ---------------------------------------------------------------------------
// launch
// ---------------------------------------------------------------------------
extern "C" void kernel_launch(void* const* d_in, const int* in_sizes, int n_in,
                              void* d_out, int out_size) {
    const float* x = (const float*)d_in[0];
    const float* w = (const float*)d_in[1];
    const float* bias = (const float*)d_in[2];
    float* out = (float*)d_out;

    cudaFuncSetAttribute(gemm_s8, cudaFuncAttributeMaxDynamicSharedMemorySize,
                         SMEM_BYTES);

    quant_x<<<M, 256>>>(x);
    quant_w<<<(N * K) / (256 * 16), 256>>>(w);

    gemm_s8<<<GRID, 256, SMEM_BYTES>>>(0, out, bias);
    gemm_s8<<<GRID, 256, SMEM_BYTES>>>(1, out, bias);
}

// round 17
// speedup vs baseline: 1.0514x; 1.0514x over previous
#include <cuda_runtime.h>
#include <cstdint>

// ============================================================================
// TernaryLinear: out[8192,4096] = x[8192,4096] @ W^T[4096,4096] + bias
//
// sm_103 plain PTX target -> legacy IMMA path (tcgen05 rejected by ptxas).
// Two exact int8 GEMMs (x = s1*a1 + (s1/254)*a2), int32 accumulation.
// Floor: 67M m16n8k32 IMMA @ ~13.6 cyc/SM ~= 3.47 ms.
// R8 (best, 3792us): 2 CTAs/SM, BM=BN=128, BK=128, warp 64x32, 3 stages.
// R9 persistent-CTA attempt REGRESSED (static imbalance + index math) ->
// reverted. R13: R8 structure + ldmatrix.m8n8.x4 fragment loads
// (24 LDS.32 -> 6 ldmatrix per ks-step) to cut issue/scoreboard overhead
// inside the mainloop.
// ============================================================================

static constexpr int M = 8192, N = 4096, K = 4096;

static constexpr int BM = 128, BN = 128, BK = 128;
static constexpr int KCH = K / BK;            // 32 k-chunks
static constexpr int NSTG = 3;
static constexpr int APITCH = BK + 16;        // 144: conflict-free
static constexpr int BPITCH = BK + 16;
static constexpr int STG_A = BM * APITCH;     // 18432
static constexpr int STG_B = BN * BPITCH;     // 18432
static constexpr int STG = STG_A + STG_B;     // 36864
static constexpr int SMEM_BYTES = STG * NSTG; // 110592 (x2 CTA = 221184 <= 228K)

// ---------------------------------------------------------------------------
// Static device scratch (allocation is forbidden)
// ---------------------------------------------------------------------------
__device__ __align__(16) int8_t g_a1[(size_t)M * K];   // 32 MB
__device__ __align__(16) int8_t g_a2[(size_t)M * K];   // 32 MB
__device__ __align__(16) int8_t g_wq[(size_t)N * K];   // 16 MB
__device__ __align__(16) int    g_o1[(size_t)M * N];   // 128 MB
__device__ float g_s1[M];

// ---------------------------------------------------------------------------
// Quantization kernels
// ---------------------------------------------------------------------------
__global__ __launch_bounds__(256) void quant_x(const float* __restrict__ x) {
    const int row = blockIdx.x;
    const int t = threadIdx.x;
    const float* xr = x + (size_t)row * K;

    float v[16];
#pragma unroll
    for (int i = 0; i < 4; i++) {
        float4 f = *reinterpret_cast<const float4*>(xr + t * 16 + i * 4);
        v[i * 4 + 0] = f.x; v[i * 4 + 1] = f.y;
        v[i * 4 + 2] = f.z; v[i * 4 + 3] = f.w;
    }
    float mx = 0.f;
#pragma unroll
    for (int i = 0; i < 16; i++) mx = fmaxf(mx, fabsf(v[i]));

    __shared__ float red[256];
    red[t] = mx;
    __syncthreads();
#pragma unroll
    for (int s = 128; s > 0; s >>= 1) {
        if (t < s) red[t] = fmaxf(red[t], red[t + s]);
        __syncthreads();
    }
    const float rmax = red[0];
    const float s1 = rmax * (1.f / 127.f);
    const float inv1 = (rmax > 0.f) ? (127.f / rmax) : 0.f;
    const float inv2 = inv1 * 254.f;
    if (t == 0) g_s1[row] = s1;

    uint32_t p1[4] = {0, 0, 0, 0}, p2[4] = {0, 0, 0, 0};
#pragma unroll
    for (int i = 0; i < 16; i++) {
        int a = __float2int_rn(v[i] * inv1);
        a = max(-127, min(127, a));
        float r = v[i] - (float)a * s1;
        int b = __float2int_rn(r * inv2);
        b = max(-127, min(127, b));
        p1[i >> 2] |= ((uint32_t)a & 0xffu) << (8 * (i & 3));
        p2[i >> 2] |= ((uint32_t)b & 0xffu) << (8 * (i & 3));
    }
    const size_t off = (size_t)row * K + t * 16;
    *reinterpret_cast<uint4*>(g_a1 + off) = *reinterpret_cast<uint4*>(p1);
    *reinterpret_cast<uint4*>(g_a2 + off) = *reinterpret_cast<uint4*>(p2);
}

__global__ __launch_bounds__(256) void quant_w(const float* __restrict__ w) {
    const size_t base = ((size_t)blockIdx.x * 256 + threadIdx.x) * 16;
    uint32_t p[4];
#pragma unroll
    for (int i = 0; i < 4; i++) {
        float4 f = *reinterpret_cast<const float4*>(w + base + i * 4);
        int a = __float2int_rn(f.x), b = __float2int_rn(f.y);
        int c = __float2int_rn(f.z), d = __float2int_rn(f.w);
        p[i] = ((uint32_t)a & 0xffu) | (((uint32_t)b & 0xffu) << 8) |
               (((uint32_t)c & 0xffu) << 16) | (((uint32_t)d & 0xffu) << 24);
    }
    *reinterpret_cast<uint4*>(g_wq + base) = *reinterpret_cast<uint4*>(p);
}

// ---------------------------------------------------------------------------
// IMMA / ldmatrix helpers
// ---------------------------------------------------------------------------
__device__ __forceinline__ void imma16832(int* c, const uint32_t* a, const uint32_t* b) {
    asm volatile(
        "mma.sync.aligned.m16n8k32.row.col.s32.s8.s8.s32 "
        "{%0,%1,%2,%3}, {%4,%5,%6,%7}, {%8,%9}, {%0,%1,%2,%3};"
        : "+r"(c[0]), "+r"(c[1]), "+r"(c[2]), "+r"(c[3])
        : "r"(a[0]), "r"(a[1]), "r"(a[2]), "r"(a[3]), "r"(b[0]), "r"(b[1]));
}

__device__ __forceinline__ void ldm_x4(uint32_t* r, const void* p) {
    uint32_t a = (uint32_t)__cvta_generic_to_shared(p);
    asm volatile(
        "ldmatrix.sync.aligned.m8n8.x4.shared.b16 {%0,%1,%2,%3}, [%4];"
        : "=r"(r[0]), "=r"(r[1]), "=r"(r[2]), "=r"(r[3]) : "r"(a));
}

__device__ __forceinline__ void cp16(void* s, const void* g) {
    uint32_t sa = (uint32_t)__cvta_generic_to_shared(s);
    asm volatile("cp.async.cg.shared.global [%0], [%1], 16;" :: "r"(sa), "l"(g));
}

// ---------------------------------------------------------------------------
// GEMM: 256 threads, CTA tile 128x128, warp tile 64x32 (2x4 warp grid),
// BK=128, 3-stage cp.async pipeline, 2 CTAs/SM, ldmatrix fragment loads.
// pass=0: o1 = a1.W (int32). pass=1: out = s1*o1 + s2*(a2.W) + bias.
// ---------------------------------------------------------------------------
__global__ __launch_bounds__(256, 2)
void gemm_s8(int pass, float* __restrict__ out, const float* __restrict__ bias) {
    extern __shared__ char smem[];
    const int tid = threadIdx.x;
    const int warp = tid >> 5, lane = tid & 31;
    const int g = lane >> 2, tig = lane & 3;     // mma group / thread-in-group

    const int bn = blockIdx.x & 31;              // n-fast: A tile reuse in L2
    const int bm = blockIdx.x >> 5;
    const int m0 = bm * BM, n0 = bn * BN;

    const int wm = (warp & 1) * 64;              // warp tile origin 64x32
    const int wn = (warp >> 1) * 32;

    // ldmatrix per-lane address components
    // A x4 tiles: [rows g..g+7 | g+8..g+15] x [bytes 0-15 | 16-31]
    const int a_row = ((lane >> 3) & 1) * 8 + (lane & 7);
    const int a_byte = (lane >> 4) * 16;
    // B x4 tiles: [cols nf0*8.. | bytes 0-15/16-31] then nf1
    const int b_row = (lane >> 4) * 8 + (lane & 7);
    const int b_byte = ((lane >> 3) & 1) * 16;

    const int8_t* Aptr = (pass ? g_a2 : g_a1) + (size_t)m0 * K;
    const int8_t* Wptr = g_wq + (size_t)n0 * K;

    // ---- pipeline load helper: 256 rows x 8 x 16B = 2048 items -----------
    auto load_stage = [&](int s, int c) {
        char* st = smem + s * STG;
        const int k0 = c * BK;
#pragma unroll
        for (int t = 0; t < 8; t++) {
            const int item = tid + t * 256;      // 0..2047
            if (item < 1024) {                   // A: 128 rows x 8 segs
                const int row = item >> 3, seg = item & 7;
                cp16(st + row * APITCH + seg * 16,
                     Aptr + (size_t)row * K + k0 + seg * 16);
            } else {                             // B: 128 rows x 8 segs
                const int bi = item - 1024;
                const int row = bi >> 3, seg = bi & 7;
                cp16(st + STG_A + row * BPITCH + seg * 16,
                     Wptr + (size_t)row * K + k0 + seg * 16);
            }
        }
        asm volatile("cp.async.commit_group;" ::: "memory");
    };

    // ---- accumulators: 4 mfrag x 4 nfrag x 4 = 64 regs --------------------
    int acc[4][4][4];
#pragma unroll
    for (int i = 0; i < 4; i++)
#pragma unroll
        for (int j = 0; j < 4; j++)
#pragma unroll
            for (int q = 0; q < 4; q++) acc[i][j][q] = 0;

    // ---- prologue: 2 chunks in flight ------------------------------------
    load_stage(0, 0);
    load_stage(1, 1);

    // ---- mainloop --------------------------------------------------------
    for (int c = 0; c < KCH; c++) {
        asm volatile("cp.async.wait_group 1;" ::: "memory");
        __syncthreads();
        if (c + 2 < KCH) {
            int s = c + 2;
            while (s >= NSTG) s -= NSTG;
            load_stage(s, c + 2);
        } else {
            asm volatile("cp.async.commit_group;" ::: "memory");
        }

        int cs = c;
        while (cs >= NSTG) cs -= NSTG;
        const char* As = smem + cs * STG;
        const char* Bs = As + STG_A;

#pragma unroll
        for (int ks = 0; ks < 4; ks++) {
            const int kb = ks * 32;
            uint32_t af[4][4];
#pragma unroll
            for (int mf = 0; mf < 4; mf++)
                ldm_x4(af[mf], As + (wm + mf * 16 + a_row) * APITCH + kb + a_byte);

            uint32_t bf[4][2];
#pragma unroll
            for (int p = 0; p < 2; p++) {
                uint32_t bq[4];
                ldm_x4(bq, Bs + (wn + p * 16 + b_row) * BPITCH + kb + b_byte);
                bf[2 * p][0] = bq[0]; bf[2 * p][1] = bq[1];
                bf[2 * p + 1][0] = bq[2]; bf[2 * p + 1][1] = bq[3];
            }
#pragma unroll
            for (int mf = 0; mf < 4; mf++)
#pragma unroll
                for (int nf = 0; nf < 4; nf++)
                    imma16832(acc[mf][nf], af[mf], bf[nf]);
        }
    }

    // ---- epilogue --------------------------------------------------------
    if (pass == 0) {
#pragma unroll
        for (int mf = 0; mf < 4; mf++) {
            const int r0 = m0 + wm + mf * 16 + g;
#pragma unroll
            for (int nf = 0; nf < 4; nf++) {
                const int col = n0 + wn + nf * 8 + tig * 2;
                *reinterpret_cast<int2*>(g_o1 + (size_t)r0 * N + col) =
                    make_int2(acc[mf][nf][0], acc[mf][nf][1]);
                *reinterpret_cast<int2*>(g_o1 + (size_t)(r0 + 8) * N + col) =
                    make_int2(acc[mf][nf][2], acc[mf][nf][3]);
            }
        }
    } else {
#pragma unroll
        for (int mf = 0; mf < 4; mf++) {
            const int r0 = m0 + wm + mf * 16 + g;
            const float s1a = g_s1[r0];
            const float s1b = g_s1[r0 + 8];
            const float s2a = s1a * (1.f / 254.f);
            const float s2b = s1b * (1.f / 254.f);
#pragma unroll
            for (int nf = 0; nf < 4; nf++) {
                const int col = n0 + wn + nf * 8 + tig * 2;
                const float2 bv = *reinterpret_cast<const float2*>(bias + col);
                int2 oa = *reinterpret_cast<const int2*>(g_o1 + (size_t)r0 * N + col);
                int2 ob = *reinterpret_cast<const int2*>(g_o1 + (size_t)(r0 + 8) * N + col);
                float2 fa, fb;
                fa.x = fmaf(s1a, (float)oa.x, fmaf(s2a, (float)acc[mf][nf][0], bv.x));
                fa.y = fmaf(s1a, (float)oa.y, fmaf(s2a, (float)acc[mf][nf][1], bv.y));
                fb.x = fmaf(s1b, (float)ob.x, fmaf(s2b, (float)acc[mf][nf][2], bv.x));
                fb.y = fmaf(s1b, (float)ob.y, fmaf(s2b, (float)acc[mf][nf][3], bv.y));
                *reinterpret_cast<float2*>(out + (size_t)r0 * N + col) = fa;
                *reinterpret_cast<float2*>(out + (size_t)(r0 + 8) * N + col) = fb;
            }
        }
    }
}

// ---------------------------------------------------------------------------
// launch
// ---------------------------------------------------------------------------
extern "C" void kernel_launch(void* const* d_in, const int* in_sizes, int n_in,
                              void* d_out, int out_size) {
    const float* x = (const float*)d_in[0];
    const float* w = (const float*)d_in[1];
    const float* bias = (const float*)d_in[2];
    float* out = (float*)d_out;

    cudaFuncSetAttribute(gemm_s8, cudaFuncAttributeMaxDynamicSharedMemorySize,
                         SMEM_BYTES);

    quant_x<<<M, 256>>>(x);
    quant_w<<<(N * K) / (256 * 16), 256>>>(w);

    const int grid = (M / BM) * (N / BN);   // 2048
    gemm_s8<<<grid, 256, SMEM_BYTES>>>(0, out, bias);
    gemm_s8<<<grid, 256, SMEM_BYTES>>>(1, out, bias);
}